// round 2
// baseline (speedup 1.0000x reference)
#include <cuda_runtime.h>

#define BB 16
#define CC 256
#define LL 8192
#define KK 3
#define NROWS (BB*CC)
#define BN_EPS 1e-5f
#define TT 16  // conv tile columns

// ---- scratch (device globals; no allocation) ----
__device__ __align__(16) float g_s[(size_t)BB*CC*LL];   // sparsemax output, 128MB
__device__ float g_sum[CC];
__device__ float g_sumsq[CC];
__device__ float g_vnorm2;
__device__ float g_a[CC];                 // z = a*x + b
__device__ float g_bb[CC];
__device__ __align__(16) float g_wT[KK*CC*CC];          // wT[k][c][o]

// ---- block reduce (256 threads), broadcasts (sum_a, sum_b) to all ----
__device__ __forceinline__ float2 blockReduce2(float a, float b, float* red) {
#pragma unroll
    for (int o = 16; o; o >>= 1) {
        a += __shfl_xor_sync(0xffffffffu, a, o);
        b += __shfl_xor_sync(0xffffffffu, b, o);
    }
    int w = threadIdx.x >> 5, lane = threadIdx.x & 31;
    __syncthreads();                 // protect red from previous use
    if (lane == 0) { red[w] = a; red[8 + w] = b; }
    __syncthreads();
    float ra = 0.f, rb = 0.f;
#pragma unroll
    for (int i = 0; i < 8; i++) { ra += red[i]; rb += red[8 + i]; }
    return make_float2(ra, rb);
}

// ---- 0: zero accumulators (must reset every launch: graph replays) ----
__global__ void kZero() {
    int t = threadIdx.x;
    if (t < CC) { g_sum[t] = 0.f; g_sumsq[t] = 0.f; }
    if (t == 0) g_vnorm2 = 0.f;
}

// ---- 1: ||v||_F^2 ----
__global__ void __launch_bounds__(256) kVnorm(const float* __restrict__ v) {
    __shared__ float red[16];
    float s = 0.f;
    for (int i = blockIdx.x * 256 + threadIdx.x; i < CC * CC * KK; i += gridDim.x * 256) {
        float t = v[i];
        s += t * t;
    }
    float2 r = blockReduce2(s, 0.f, red);
    if (threadIdx.x == 0) atomicAdd(&g_vnorm2, r.x);
}

// ---- 2: per-channel sum / sumsq (one block per (b,c) row) ----
__global__ void __launch_bounds__(256) kStats(const float* __restrict__ x) {
    __shared__ float red[16];
    int row = blockIdx.x;
    int c = row & (CC - 1);
    const float4* xr = (const float4*)(x + (size_t)row * LL);
    float s = 0.f, q = 0.f;
#pragma unroll
    for (int i = 0; i < 8; i++) {
        float4 v = xr[threadIdx.x + 256 * i];
        s += (v.x + v.y) + (v.z + v.w);
        q += (v.x * v.x + v.y * v.y) + (v.z * v.z + v.w * v.w);
    }
    float2 r = blockReduce2(s, q, red);
    if (threadIdx.x == 0) {
        atomicAdd(&g_sum[c], r.x);
        atomicAdd(&g_sumsq[c], r.y);
    }
}

// ---- 3: finalize channel affine coefficients ----
__global__ void kChan(const float* __restrict__ bnw, const float* __restrict__ bnb) {
    int c = threadIdx.x;
    const float inv = 1.0f / (float)(BB * LL);
    float mean = g_sum[c] * inv;
    float var = fmaxf(g_sumsq[c] * inv - mean * mean, 0.f);
    float a = bnw[c] * rsqrtf(var + BN_EPS);
    g_a[c] = a;
    g_bb[c] = fmaf(-mean, a, bnb[c]);
}

// ---- 4: build wT[k][c][o] = g * v[o][c][k] / ||v||_F ----
__global__ void __launch_bounds__(256) kWT(const float* __restrict__ v, const float* __restrict__ g) {
    int idx = blockIdx.x * 256 + threadIdx.x;  // exactly 3*256*256 threads
    float scale = g[0] * rsqrtf(g_vnorm2);
    int k = idx >> 16;
    int rem = idx & 65535;
    int c = rem >> 8;
    int o = rem & 255;
    g_wT[idx] = v[o * (CC * KK) + c * KK + k] * scale;
}

// ---- 5: sparsemax per row (bisection on candidate set) ----
__global__ void __launch_bounds__(256) kSparsemax(const float* __restrict__ x) {
    __shared__ float cand[LL];
    __shared__ float red[16];
    __shared__ int cnt;
    int row = blockIdx.x;
    int c = row & (CC - 1);
    float a = g_a[c], bco = g_bb[c];
    const float4* xr = (const float4*)(x + (size_t)row * LL);
    float z[32];
    float zmax = -1e30f;
#pragma unroll
    for (int i = 0; i < 8; i++) {
        float4 v = xr[threadIdx.x + 256 * i];
        float z0 = fmaf(a, v.x, bco), z1 = fmaf(a, v.y, bco);
        float z2 = fmaf(a, v.z, bco), z3 = fmaf(a, v.w, bco);
        z[4 * i + 0] = z0; z[4 * i + 1] = z1; z[4 * i + 2] = z2; z[4 * i + 3] = z3;
        zmax = fmaxf(zmax, fmaxf(fmaxf(z0, z1), fmaxf(z2, z3)));
    }
    // block max
#pragma unroll
    for (int o = 16; o; o >>= 1) zmax = fmaxf(zmax, __shfl_xor_sync(0xffffffffu, zmax, o));
    int w = threadIdx.x >> 5, lane = threadIdx.x & 31;
    if (lane == 0) red[w] = zmax;
    if (threadIdx.x == 0) cnt = 0;
    __syncthreads();
    zmax = red[0];
#pragma unroll
    for (int i = 1; i < 8; i++) zmax = fmaxf(zmax, red[i]);

    float lo = zmax - 1.0f, hi = zmax;
    // only z > zmax-1 can ever be in the support: compact candidates
#pragma unroll
    for (int i = 0; i < 32; i++) {
        if (z[i] > lo) {
            int p = atomicAdd(&cnt, 1);
            cand[p] = z[i];
        }
    }
    __syncthreads();
    int m = cnt;

    for (int it = 0; it < 28; it++) {
        float mid = 0.5f * (lo + hi);
        float s = 0.f, n = 0.f;
        for (int i = threadIdx.x; i < m; i += 256) {
            float zz = cand[i];
            if (zz > mid) { s += zz; n += 1.f; }
        }
        float2 r = blockReduce2(s, n, red);
        float f = r.x - mid * r.y - 1.0f;
        if (f > 0.f) lo = mid; else hi = mid;
    }
    // exact tau on the converged support
    {
        float s = 0.f, n = 0.f;
        for (int i = threadIdx.x; i < m; i += 256) {
            float zz = cand[i];
            if (zz > lo) { s += zz; n += 1.f; }
        }
        float2 r = blockReduce2(s, n, red);
        float tau = (r.x - 1.0f) / fmaxf(r.y, 1.0f);
        float4* so = (float4*)(g_s + (size_t)row * LL);
#pragma unroll
        for (int i = 0; i < 8; i++) {
            float4 o4;
            o4.x = fmaxf(z[4 * i + 0] - tau, 0.f);
            o4.y = fmaxf(z[4 * i + 1] - tau, 0.f);
            o4.z = fmaxf(z[4 * i + 2] - tau, 0.f);
            o4.w = fmaxf(z[4 * i + 3] - tau, 0.f);
            so[threadIdx.x + 256 * i] = o4;
        }
    }
}

// ---- 6: sparse conv + relu ----
// block = (b, tile of TT output cols). tile has TT+2 input cols.
__global__ void __launch_bounds__(256) kConv(float* __restrict__ y) {
    __shared__ __align__(16) float tile[CC][TT + 3];              // pitch 19 (gcd(19,32)=1)
    __shared__ __align__(16) unsigned short pool[(TT + 2) * 256]; // per-col nonzero channel lists
    __shared__ int cnt[TT + 2];
    __shared__ __align__(16) float tr[TT][260];                   // tr[lt][o], pitch 260 (16B-aligned)

    int b = blockIdx.y;
    int l0 = blockIdx.x * TT;
    int tid = threadIdx.x, warp = tid >> 5, lane = tid & 31;

    // load s tile (coalesced-ish per channel row)
    const float* sb = g_s + (size_t)b * CC * LL;
    for (int cch = warp; cch < CC; cch += 8) {
        if (lane < TT + 2) {
            int gj = l0 - 1 + lane;
            const float* rp = sb + (size_t)cch * LL;
            tile[cch][lane] = (gj >= 0 && gj < LL) ? rp[gj] : 0.f;
        }
    }
    if (tid < TT + 2) cnt[tid] = 0;
    __syncthreads();

    // compact nonzero channels per input column (thread == channel)
    {
        float* myrow = tile[tid];
#pragma unroll
        for (int j = 0; j < TT + 2; j++) {
            if (myrow[j] > 0.f) {
                int p = atomicAdd(&cnt[j], 1);
                pool[(j << 8) + p] = (unsigned short)tid;
            }
        }
    }
    __syncthreads();

    // compute: 4 column-groups of 64 threads; each thread does 4 outputs (float4 wT)
    int g4 = tid >> 6;        // column group 0..3
    int t = tid & 63;         // 0..63 -> outputs o0..o0+3
#pragma unroll 1
    for (int it = 0; it < TT / 4; it++) {
        int lt = (it << 2) + g4;      // output col in tile
        float4 acc = make_float4(0.f, 0.f, 0.f, 0.f);
#pragma unroll
        for (int k = 0; k < KK; k++) {
            int j = lt + k;           // input col in tile
            int n = cnt[j];
            const unsigned short* pl = &pool[j << 8];
            const float4* wk = (const float4*)(g_wT + (k << 16));
            for (int e = 0; e < n; e++) {
                int ch = pl[e];
                float val = tile[ch][j];
                float4 wv = wk[(ch << 6) + t];  // wT[k][ch][4t..4t+3]
                acc.x = fmaf(wv.x, val, acc.x);
                acc.y = fmaf(wv.y, val, acc.y);
                acc.z = fmaf(wv.z, val, acc.z);
                acc.w = fmaf(wv.w, val, acc.w);
            }
        }
        *(float4*)&tr[lt][t << 2] = acc;
    }
    __syncthreads();

    // coalesced write with relu: warp writes 2 rows x 16 cols per iteration
    float* yb = y + (size_t)b * CC * LL + l0;
#pragma unroll
    for (int r = 0; r < 16; r++) {
        int o = r * 16 + warp * 2 + (lane >> 4);
        int col = lane & 15;
        yb[(size_t)o * LL + col] = fmaxf(tr[col][o], 0.f);
    }
}

extern "C" void kernel_launch(void* const* d_in, const int* in_sizes, int n_in,
                              void* d_out, int out_size) {
    const float* x   = (const float*)d_in[0];
    const float* bnw = (const float*)d_in[1];
    const float* bnb = (const float*)d_in[2];
    const float* v   = (const float*)d_in[3];
    const float* g   = (const float*)d_in[4];
    float* y = (float*)d_out;

    kZero<<<1, 256>>>();
    kVnorm<<<96, 256>>>(v);
    kStats<<<NROWS, 256>>>(x);
    kChan<<<1, 256>>>(bnw, bnb);
    kWT<<<KK * CC * CC / 256, 256>>>(v, g);
    kSparsemax<<<NROWS, 256>>>(x);
    kConv<<<dim3(LL / TT, BB), 256>>>(y);
}